// round 1
// baseline (speedup 1.0000x reference)
#include <cuda_runtime.h>

// ----------------------------------------------------------------------------
// Clebsch-Gordan sparse product, LMAX=5, TAU=32, BATCH=32.
// Strategy: group the 111 (l,l1,l2) tuples by (l1,l2) pair (36 pairs). For each
// (b, t1, t2) a thread computes all complex pair products a[m1]*b[m2] once and
// accumulates them into every valid output l with compile-time CG coefficients
// (immediate-form FFMA). Outputs are staged through shared memory per warp so
// global stores are fully coalesced float4s.
// ----------------------------------------------------------------------------

#define LMAXV 5
#define ROWF  1579008   // output floats per batch row
// grid: 36 pairs * 32 batches * 4 quarters
#define NBLOCKS (36*32*4)

// ---------------- constexpr CG machinery (compile-time only) ----------------

__host__ __device__ constexpr double cfact(int n) {
    double r = 1.0;
    for (int i = 2; i <= n; ++i) r *= (double)i;
    return r;
}

__host__ __device__ constexpr double csqrt_(double x) {
    if (x <= 0.0) return 0.0;
    double g = (x >= 1.0) ? x : 1.0;
    for (int i = 0; i < 160; ++i) g = 0.5 * (g + x / g);
    return g;
}

__host__ __device__ constexpr double cg_coef(int j1, int m1, int j2, int m2, int j3, int m3) {
    if (m1 + m2 != m3) return 0.0;
    int lo = (j1 > j2) ? (j1 - j2) : (j2 - j1);
    if (j3 < lo || j3 > j1 + j2) return 0.0;
    double pref = csqrt_((2.0 * j3 + 1.0) * cfact(j3 + j1 - j2) * cfact(j3 - j1 + j2)
                         * cfact(j1 + j2 - j3) / cfact(j1 + j2 + j3 + 1));
    pref = pref * csqrt_(cfact(j3 + m3) * cfact(j3 - m3) * cfact(j1 - m1) * cfact(j1 + m1)
                         * cfact(j2 - m2) * cfact(j2 + m2));
    double s = 0.0;
    for (int k = 0; k <= j1 + j2 - j3; ++k) {
        int a2 = j1 + j2 - j3 - k;
        int a3 = j1 - m1 - k;
        int a4 = j2 + m2 - k;
        int a5 = j3 - j2 + m1 + k;
        int a6 = j3 - j1 - m2 + k;
        if (a2 < 0 || a3 < 0 || a4 < 0 || a5 < 0 || a6 < 0) continue;
        double den = cfact(k) * cfact(a2) * cfact(a3) * cfact(a4) * cfact(a5) * cfact(a6);
        s += ((k & 1) ? -1.0 : 1.0) / den;
    }
    return pref * s;
}

// output base (in floats, within one batch row) of tuple (L, L1, L2),
// enumeration order: l outer, l1, l2 inner (matches reference LTUPLES order)
__host__ __device__ constexpr int out_base_f(int L1, int L2, int L) {
    int off = 0;
    for (int l = 0; l <= LMAXV; ++l)
        for (int l1 = 0; l1 <= LMAXV; ++l1)
            for (int l2 = 0; l2 <= LMAXV; ++l2) {
                int lo = (l1 > l2) ? (l1 - l2) : (l2 - l1);
                if (!(lo <= l && l <= l1 + l2)) continue;
                if (l == L && l1 == L1 && l2 == L2) return off;
                off += 1024 * (2 * l + 1) * 2;
            }
    return 0;
}

// ---------------- unrolled accumulation metaprogram ----------------

template <int L1, int L2, int M1, int M2, int L>
__device__ __forceinline__ void accum_l(float kr, float ki, float* outr, float* outi) {
    constexpr int LO = (L1 > L2) ? (L1 - L2) : (L2 - L1);
    constexpr int HI = (L1 + L2 < LMAXV) ? (L1 + L2) : LMAXV;
    if constexpr (L <= HI) {
        constexpr int M = M1 + M2;
        if constexpr (M >= -L && M <= L) {
            constexpr double cd = cg_coef(L1, M1, L2, M2, L, M);
            if constexpr (cd != 0.0) {
                constexpr float c = (float)cd;
                constexpr int idx = L * L - LO * LO + (M + L);
                outr[idx] = fmaf(c, kr, outr[idx]);
                outi[idx] = fmaf(c, ki, outi[idx]);
            }
        }
        accum_l<L1, L2, M1, M2, L + 1>(kr, ki, outr, outi);
    }
}

template <int L1, int L2, int M1, int M2>
__device__ __forceinline__ void m2_chain(const float2* Bv, float ar, float ai,
                                         float* outr, float* outi) {
    float br = Bv[M2 + L2].x;
    float bi = Bv[M2 + L2].y;
    float u = ai * bi;
    float kr = fmaf(ar, br, -u);
    float v = ai * br;
    float ki = fmaf(ar, bi, v);
    constexpr int LO = (L1 > L2) ? (L1 - L2) : (L2 - L1);
    constexpr int M = M1 + M2;
    constexpr int AM = (M < 0) ? -M : M;
    constexpr int LS = (AM > LO) ? AM : LO;
    accum_l<L1, L2, M1, M2, LS>(kr, ki, outr, outi);
    if constexpr (M2 < L2) m2_chain<L1, L2, M1, M2 + 1>(Bv, ar, ai, outr, outi);
}

template <int L1, int L2, int M1>
__device__ __forceinline__ void row_step(const float2* A, const float2* Bv,
                                         float* outr, float* outi) {
    float ar = A[M1 + L1].x;
    float ai = A[M1 + L1].y;
    m2_chain<L1, L2, M1, -L2>(Bv, ar, ai, outr, outi);
    if constexpr (M1 < L1) row_step<L1, L2, M1 + 1>(A, Bv, outr, outi);
}

// ---------------- staged store (coalesced) ----------------

template <int L1, int L2, int L>
__device__ __forceinline__ void store_all(const float* outr, const float* outi,
                                          float* stage, float* outb, int lane, int t1) {
    constexpr int LO = (L1 > L2) ? (L1 - L2) : (L2 - L1);
    constexpr int HI = (L1 + L2 < LMAXV) ? (L1 + L2) : LMAXV;
    if constexpr (L <= HI) {
        constexpr int TW = 2 * L + 1;
        constexpr int K = 2 * TW;          // floats per (t) chunk
        float2* st2 = (float2*)stage;
#pragma unroll
        for (int m = 0; m < TW; ++m) {
            st2[lane * TW + m] = make_float2(outr[L * L - LO * LO + m],
                                             outi[L * L - LO * LO + m]);
        }
        __syncwarp();
        constexpr int OB = out_base_f(L1, L2, L);
        float4* g4 = (float4*)(outb + OB + t1 * 32 * K);
        const float4* s4 = (const float4*)stage;
        constexpr int N4 = 8 * K;          // 32*K/4 float4s
#pragma unroll
        for (int j = lane; j < N4; j += 32) g4[j] = s4[j];
        __syncwarp();
        store_all<L1, L2, L + 1>(outr, outi, stage, outb, lane, t1);
    }
}

// ---------------- per-pair block body ----------------

template <int L1, int L2>
__device__ __forceinline__ void block_work(const float* __restrict__ fs,
                                           float* __restrict__ out,
                                           float* s1, float* s2, float* stage,
                                           int q, int b) {
    const int tid = threadIdx.x;
    const int warp = tid >> 5;
    const int lane = tid & 31;
    constexpr int LO = (L1 > L2) ? (L1 - L2) : (L2 - L1);
    constexpr int HI = (L1 + L2 < LMAXV) ? (L1 + L2) : LMAXV;
    constexpr int NOUT = (HI + 1) * (HI + 1) - LO * LO;

    // stage input fragments (each is 32*(2l+1) float2, contiguous in gmem)
    {
        const float4* i1 = (const float4*)(fs + (size_t)b * 2304 + 64 * L1 * L1);
        const float4* i2 = (const float4*)(fs + (size_t)b * 2304 + 64 * L2 * L2);
        constexpr int N1 = 16 * (2 * L1 + 1);
        constexpr int N2 = 16 * (2 * L2 + 1);
#pragma unroll
        for (int j = tid; j < N1; j += 128) ((float4*)s1)[j] = i1[j];
#pragma unroll
        for (int j = tid; j < N2; j += 128) ((float4*)s2)[j] = i2[j];
    }
    __syncthreads();

    float* outb = out + (size_t)b * ROWF;
    float* wstage = stage + warp * 704;

#pragma unroll
    for (int iter = 0; iter < 2; ++iter) {
        const int t1 = q * 8 + iter * 4 + warp;

        float2 A[2 * L1 + 1];
        float2 Bv[2 * L2 + 1];
        {
            const float2* av = (const float2*)s1 + t1 * (2 * L1 + 1);
            const float2* bv = (const float2*)s2 + lane * (2 * L2 + 1);
#pragma unroll
            for (int i = 0; i < 2 * L1 + 1; ++i) A[i] = av[i];
#pragma unroll
            for (int i = 0; i < 2 * L2 + 1; ++i) Bv[i] = bv[i];
        }

        float outr[NOUT], outi[NOUT];
#pragma unroll
        for (int i = 0; i < NOUT; ++i) { outr[i] = 0.f; outi[i] = 0.f; }

        row_step<L1, L2, -L1>(A, Bv, outr, outi);

        store_all<L1, L2, LO>(outr, outi, wstage, outb, lane, t1);
    }
}

// ---------------- kernel ----------------

__global__ void __launch_bounds__(128)
cg_sparse_kernel(const float* __restrict__ fs, float* __restrict__ out) {
    __shared__ __align__(16) float s1[704];
    __shared__ __align__(16) float s2[704];
    __shared__ __align__(16) float stage[4 * 704];

    const int bx = blockIdx.x;
    const int q = bx & 3;
    const int b = (bx >> 2) & 31;
    const int p = bx >> 7;   // 0..35, p = l1*6 + l2

#define PCASE(P, A_, B_) case P: block_work<A_, B_>(fs, out, s1, s2, stage, q, b); break;
    switch (p) {
        PCASE(0, 0, 0)  PCASE(1, 0, 1)  PCASE(2, 0, 2)  PCASE(3, 0, 3)  PCASE(4, 0, 4)  PCASE(5, 0, 5)
        PCASE(6, 1, 0)  PCASE(7, 1, 1)  PCASE(8, 1, 2)  PCASE(9, 1, 3)  PCASE(10, 1, 4) PCASE(11, 1, 5)
        PCASE(12, 2, 0) PCASE(13, 2, 1) PCASE(14, 2, 2) PCASE(15, 2, 3) PCASE(16, 2, 4) PCASE(17, 2, 5)
        PCASE(18, 3, 0) PCASE(19, 3, 1) PCASE(20, 3, 2) PCASE(21, 3, 3) PCASE(22, 3, 4) PCASE(23, 3, 5)
        PCASE(24, 4, 0) PCASE(25, 4, 1) PCASE(26, 4, 2) PCASE(27, 4, 3) PCASE(28, 4, 4) PCASE(29, 4, 5)
        PCASE(30, 5, 0) PCASE(31, 5, 1) PCASE(32, 5, 2) PCASE(33, 5, 3) PCASE(34, 5, 4) PCASE(35, 5, 5)
        default: break;
    }
#undef PCASE
}

extern "C" void kernel_launch(void* const* d_in, const int* in_sizes, int n_in,
                              void* d_out, int out_size) {
    const float* fs = (const float*)d_in[0];
    float* out = (float*)d_out;
    cg_sparse_kernel<<<NBLOCKS, 128>>>(fs, out);
}